// round 1
// baseline (speedup 1.0000x reference)
#include <cuda_runtime.h>
#include <cstddef>

// NonLocalBlock: B=4, H=W=64, C=256, D=32, N=H*W=4096
// out = gamma * ((flashattn(k=x@Wg rows, q=x@Wf cols, v=x@Wh)) @ Wv) + x
//   beta[n,m] = softmax_m(k_n . q_m);  o[n] = sum_m beta[n,m] v[m]

#define NB      4
#define NTOK    4096
#define NC      256
#define ND      32
#define NROWS   (NB*NTOK)      // 16384

// ---------------- device scratch (no allocations allowed) ----------------
__device__ float g_q[NROWS * ND];
__device__ float g_k[NROWS * ND];
__device__ float g_v[NROWS * ND];
__device__ float g_o[NROWS * ND];

// =========================================================================
// Stage 1: q,k,v = x @ [Wf|Wg|Wh]    (16384 x 256) @ (256 x 96)
// CTA: 128 rows, all 96 cols. 256 threads as (ty 0..15, tx 0..15),
// each thread: 8 rows x 6 cols.
// =========================================================================
__global__ __launch_bounds__(256, 1)
void qkv_kernel(const float* __restrict__ x,
                const float* __restrict__ Wf,
                const float* __restrict__ Wg,
                const float* __restrict__ Wh)
{
    __shared__ float Xs[128 * 33];   // [row][c] padded
    __shared__ float Ws[32 * 97];    // [c][j] padded, j in 0..95

    const int tid = threadIdx.x;
    const int tx  = tid & 15;
    const int ty  = tid >> 4;
    const int row0 = blockIdx.x * 128;

    float acc[8][6];
#pragma unroll
    for (int r = 0; r < 8; ++r)
#pragma unroll
        for (int cc = 0; cc < 6; ++cc) acc[r][cc] = 0.0f;

    for (int c0 = 0; c0 < NC; c0 += 32) {
        __syncthreads();
        // load 128x32 chunk of x
        {
            const int c  = tid & 31;
            const int i0 = tid >> 5;
#pragma unroll
            for (int p = 0; p < 16; ++p) {
                int i = i0 + p * 8;
                Xs[i * 33 + c] = x[(size_t)(row0 + i) * NC + c0 + c];
            }
        }
        // load 32x96 chunk of combined weights
        for (int idx = tid; idx < 32 * 96; idx += 256) {
            int c = idx / 96, j = idx % 96;
            const float* W = (j < 32) ? Wf : (j < 64) ? Wg : Wh;
            Ws[c * 97 + j] = W[(size_t)(c0 + c) * ND + (j & 31)];
        }
        __syncthreads();

#pragma unroll 4
        for (int d = 0; d < 32; ++d) {
            float xf[8], wf[6];
#pragma unroll
            for (int r = 0; r < 8; ++r)  xf[r]  = Xs[(ty * 8 + r) * 33 + d];
#pragma unroll
            for (int cc = 0; cc < 6; ++cc) wf[cc] = Ws[d * 97 + tx + 16 * cc];
#pragma unroll
            for (int r = 0; r < 8; ++r)
#pragma unroll
                for (int cc = 0; cc < 6; ++cc)
                    acc[r][cc] += xf[r] * wf[cc];
        }
    }

#pragma unroll
    for (int r = 0; r < 8; ++r) {
        int row = row0 + ty * 8 + r;
#pragma unroll
        for (int cc = 0; cc < 6; ++cc) {
            int j = tx + 16 * cc;
            float* dst = (j < 32) ? g_q : (j < 64) ? g_k : g_v;
            dst[(size_t)row * ND + (j & 31)] = acc[r][cc];
        }
    }
}

// =========================================================================
// Stage 2: flash attention, fp32 SIMT.
// CTA handles 128 "n" rows (keyed by k) of one batch; loops over 4096 m in
// tiles of 128 (q columns / v rows). Threads 256 as (ty,tx) 16x16:
//   S microtile: thread (ty,tx) owns S[ty*8+r][tx*8+c]  (8x8)
//   O microtile: thread (ty,tx) owns O[ty*8+r][tx*2+cc] (8x2), D=32
// Row i's 16 column-owners all live in one warp -> shfl butterfly reductions.
// =========================================================================
#define FLASH_SMEM_FLOATS (32*132 + 32*132 + 128*34 + 128*132)
#define FLASH_SMEM_BYTES  (FLASH_SMEM_FLOATS * 4)

__global__ __launch_bounds__(256, 1)
void flash_kernel()
{
    extern __shared__ float sm[];
    float* Kst = sm;                    // [32][132]  K tile transposed (d-major)
    float* Qst = Kst + 32 * 132;        // [32][132]  Q tile transposed
    float* Vs  = Qst + 32 * 132;        // [128][34]  V tile row-major
    float* Ps  = Vs  + 128 * 34;        // [128][132] P = exp(S - m) tile

    const int b   = blockIdx.y;
    const int n0  = blockIdx.x * 128;
    const int tid = threadIdx.x;
    const int tx  = tid & 15;
    const int ty  = tid >> 4;

    const float* Kb = g_k + (size_t)b * NTOK * ND;
    const float* Qb = g_q + (size_t)b * NTOK * ND;
    const float* Vb = g_v + (size_t)b * NTOK * ND;

    // Load K row-tile once, transposed: Kst[d][i] = Kb[(n0+i)*32 + d]
    {
        const int d  = tid & 31;
        const int i0 = tid >> 5;
#pragma unroll
        for (int p = 0; p < 16; ++p) {
            int i = i0 + p * 8;
            Kst[d * 132 + i] = Kb[(size_t)(n0 + i) * ND + d];
        }
    }

    float m_run[8], l_run[8], o0[8], o1[8];
#pragma unroll
    for (int r = 0; r < 8; ++r) {
        m_run[r] = -1e30f; l_run[r] = 0.0f; o0[r] = 0.0f; o1[r] = 0.0f;
    }

    for (int m0 = 0; m0 < NTOK; m0 += 128) {
        __syncthreads();   // previous iteration done reading Qst/Vs/Ps
        // Load Q tile transposed + V tile
        {
            const int d  = tid & 31;
            const int j0 = tid >> 5;
#pragma unroll
            for (int p = 0; p < 16; ++p) {
                int j = j0 + p * 8;
                float qv = Qb[(size_t)(m0 + j) * ND + d];
                float vv = Vb[(size_t)(m0 + j) * ND + d];
                Qst[d * 132 + j] = qv;
                Vs[j * 34 + d]   = vv;
            }
        }
        __syncthreads();

        // ---- S = K_tile @ Q_tile^T ----
        float acc[8][8];
#pragma unroll
        for (int r = 0; r < 8; ++r)
#pragma unroll
            for (int c = 0; c < 8; ++c) acc[r][c] = 0.0f;

#pragma unroll 8
        for (int d = 0; d < 32; ++d) {
            float4 a0 = *(const float4*)&Kst[d * 132 + ty * 8];
            float4 a1 = *(const float4*)&Kst[d * 132 + ty * 8 + 4];
            float4 b0 = *(const float4*)&Qst[d * 132 + tx * 8];
            float4 b1 = *(const float4*)&Qst[d * 132 + tx * 8 + 4];
            float a[8] = {a0.x, a0.y, a0.z, a0.w, a1.x, a1.y, a1.z, a1.w};
            float bb[8] = {b0.x, b0.y, b0.z, b0.w, b1.x, b1.y, b1.z, b1.w};
#pragma unroll
            for (int r = 0; r < 8; ++r)
#pragma unroll
                for (int c = 0; c < 8; ++c)
                    acc[r][c] += a[r] * bb[c];
        }

        // ---- online softmax over the 128-wide tile ----
#pragma unroll
        for (int r = 0; r < 8; ++r) {
            float mx = acc[r][0];
#pragma unroll
            for (int c = 1; c < 8; ++c) mx = fmaxf(mx, acc[r][c]);
#pragma unroll
            for (int s = 8; s >= 1; s >>= 1)
                mx = fmaxf(mx, __shfl_xor_sync(0xffffffffu, mx, s));
            float m_new = fmaxf(m_run[r], mx);
            float f = __expf(m_run[r] - m_new);
            m_run[r] = m_new;

            float sum = 0.0f;
#pragma unroll
            for (int c = 0; c < 8; ++c) {
                acc[r][c] = __expf(acc[r][c] - m_new);
                sum += acc[r][c];
            }
#pragma unroll
            for (int s = 8; s >= 1; s >>= 1)
                sum += __shfl_xor_sync(0xffffffffu, sum, s);

            l_run[r] = l_run[r] * f + sum;
            o0[r] *= f;
            o1[r] *= f;

            // store P row segment (conflict-free STS.128: lanes tx stride 32B)
            *(float4*)&Ps[(ty * 8 + r) * 132 + tx * 8] =
                make_float4(acc[r][0], acc[r][1], acc[r][2], acc[r][3]);
            *(float4*)&Ps[(ty * 8 + r) * 132 + tx * 8 + 4] =
                make_float4(acc[r][4], acc[r][5], acc[r][6], acc[r][7]);
        }
        __syncthreads();

        // ---- O += P @ V ----  (o cols d = tx*2 + {0,1})
#pragma unroll 4
        for (int m = 0; m < 128; m += 4) {
            float2 v0 = *(const float2*)&Vs[(m + 0) * 34 + tx * 2];
            float2 v1 = *(const float2*)&Vs[(m + 1) * 34 + tx * 2];
            float2 v2 = *(const float2*)&Vs[(m + 2) * 34 + tx * 2];
            float2 v3 = *(const float2*)&Vs[(m + 3) * 34 + tx * 2];
#pragma unroll
            for (int r = 0; r < 8; ++r) {
                float4 p = *(const float4*)&Ps[(ty * 8 + r) * 132 + m];
                o0[r] += p.x * v0.x; o1[r] += p.x * v0.y;
                o0[r] += p.y * v1.x; o1[r] += p.y * v1.y;
                o0[r] += p.z * v2.x; o1[r] += p.z * v2.y;
                o0[r] += p.w * v3.x; o1[r] += p.w * v3.y;
            }
        }
    }

    // epilogue: normalize and write o
#pragma unroll
    for (int r = 0; r < 8; ++r) {
        float inv = 1.0f / l_run[r];
        int row = n0 + ty * 8 + r;
        float2 res = make_float2(o0[r] * inv, o1[r] * inv);
        *(float2*)&g_o[((size_t)b * NTOK + row) * ND + tx * 2] = res;
    }
}

// =========================================================================
// Stage 3: out = gamma * (o @ Wv) + x     (16384 x 32) @ (32 x 256)
// CTA: 64 rows x 256 cols, 256 threads (ty,tx): 4 rows x 16 cols each.
// =========================================================================
__global__ __launch_bounds__(256, 1)
void out_kernel(const float* __restrict__ x,
                const float* __restrict__ Wv,
                const float* __restrict__ gamma,
                float* __restrict__ out)
{
    __shared__ float Wvs[32 * 257];   // [d][c]
    __shared__ float Os[64 * 33];     // [row][d]

    const int tid = threadIdx.x;
    const int tx  = tid & 15;
    const int ty  = tid >> 4;
    const int row0 = blockIdx.x * 64;

    for (int idx = tid; idx < 32 * 256; idx += 256) {
        int d = idx >> 8, c = idx & 255;
        Wvs[d * 257 + c] = Wv[idx];
    }
    {
        const int d  = tid & 31;
        const int i0 = tid >> 5;
#pragma unroll
        for (int p = 0; p < 8; ++p) {
            int i = i0 + p * 8;
            Os[i * 33 + d] = g_o[(size_t)(row0 + i) * ND + d];
        }
    }
    __syncthreads();

    float acc[4][16];
#pragma unroll
    for (int r = 0; r < 4; ++r)
#pragma unroll
        for (int cc = 0; cc < 16; ++cc) acc[r][cc] = 0.0f;

#pragma unroll 4
    for (int d = 0; d < 32; ++d) {
        float of[4], wf[16];
#pragma unroll
        for (int r = 0; r < 4; ++r)  of[r]  = Os[(ty * 4 + r) * 33 + d];
#pragma unroll
        for (int cc = 0; cc < 16; ++cc) wf[cc] = Wvs[d * 257 + tx + 16 * cc];
#pragma unroll
        for (int r = 0; r < 4; ++r)
#pragma unroll
            for (int cc = 0; cc < 16; ++cc)
                acc[r][cc] += of[r] * wf[cc];
    }

    const float g = gamma[0];
#pragma unroll
    for (int r = 0; r < 4; ++r) {
        size_t base = (size_t)(row0 + ty * 4 + r) * NC;
#pragma unroll
        for (int cc = 0; cc < 16; ++cc) {
            int c = tx + 16 * cc;
            out[base + c] = g * acc[r][cc] + x[base + c];
        }
    }
}

// =========================================================================
extern "C" void kernel_launch(void* const* d_in, const int* in_sizes, int n_in,
                              void* d_out, int out_size)
{
    const float* x     = (const float*)d_in[0];
    const float* Wf    = (const float*)d_in[1];
    const float* Wg    = (const float*)d_in[2];
    const float* Wh    = (const float*)d_in[3];
    const float* Wv    = (const float*)d_in[4];
    const float* gamma = (const float*)d_in[5];
    float* out = (float*)d_out;

    qkv_kernel<<<NROWS / 128, 256>>>(x, Wf, Wg, Wh);

    cudaFuncSetAttribute(flash_kernel,
                         cudaFuncAttributeMaxDynamicSharedMemorySize,
                         FLASH_SMEM_BYTES);
    flash_kernel<<<dim3(NTOK / 128, NB), 256, FLASH_SMEM_BYTES>>>();

    out_kernel<<<NROWS / 64, 256>>>(x, Wv, gamma, out);
}